// round 12
// baseline (speedup 1.0000x reference)
#include <cuda_runtime.h>
#include <cstdint>

// ======================== R12: CALIBRATED PROBE ROUND =========================
// R6 champion kernel, byte-identical, PLUS a ~1100-cycle serial dependent FMA
// chain inserted on the gate path of BOTH layers (numerically inert).
// Purpose: measure Δdur = 4096 * chain_cycles / clock  => effective SM clock and
// whether the gate path is on the binding chain. See analysis for decision tree.
// ==============================================================================

// ---------------- problem constants ----------------
#define TSEQ   4096
#define EMB    300
#define HID    500
#define HP     512
#define GATES  2000
#define NCLS   90

// ---------------- persistent-kernel config (R6 champion) ----------------
#define NB0    50
#define U0     10
#define RPW0   5
#define NB1    84
#define U1     6
#define RPW1   6
#define NBLK   (NB0 + NB1)
#define THREADS 256

#define NGRP   8
__device__ __forceinline__ int quota1(int g) { return (g < 2) ? 7 : 6; }
__device__ __forceinline__ int quota2(int g) { return (g < 4) ? 11 : 10; }

// probe chain length (serial fmaf, 4 cyc each)
#define PROBE_LEN 256

// ---------------- device scratch ----------------
__device__ float g_xp0[(size_t)TSEQ * GATES];
__device__ float g_h1[(TSEQ + 1) * HP];
__device__ float g_h2[(TSEQ + 1) * HP];
__device__ int   g_c1[(TSEQ + 1) * NGRP];
__device__ int   g_c2[(TSEQ + 1) * NGRP];
__device__ float g_Wt[EMB * GATES];

// ---------------- acquire/release primitives ----------------
__device__ __forceinline__ int ld_acq(const int* p) {
    int v;
    asm volatile("ld.acquire.gpu.global.b32 %0, [%1];" : "=r"(v) : "l"(p) : "memory");
    return v;
}
__device__ __forceinline__ void red_release(int* p) {
    asm volatile("red.release.gpu.global.add.u32 [%0], 1;" :: "l"(p) : "memory");
}

// numerically-inert serial dependency chain: ~PROBE_LEN*4 cycles, result
// magnitude ~|seed|, scaled by 1e-35 so it vanishes below fp32 resolution of h.
__device__ __forceinline__ float probe_chain(float seed) {
    float z = seed;
#pragma unroll 32
    for (int it = 0; it < PROBE_LEN; it++)
        z = fmaf(z, 0.99999988f, 1e-30f);
    return z * 1e-35f;
}

// ---------------- init: reset counters every replay ----------------
__global__ void k_init() {
    const int n = (TSEQ + 1) * NGRP;
    for (int i = blockIdx.x * blockDim.x + threadIdx.x; i < 2 * n;
         i += gridDim.x * blockDim.x) {
        if (i < n) g_c1[i] = (i < NGRP) ? quota1(i) : 0;
        else { int j = i - n; g_c2[j] = (j < NGRP) ? quota2(j) : 0; }
    }
}

// ---------------- transpose W_ih0 [2000,300] -> [300,2000] ----------------
__global__ void k_transpose(const float* __restrict__ W) {
    int idx = blockIdx.x * 256 + threadIdx.x;
    if (idx < EMB * GATES) {
        int e = idx / GATES;
        int g = idx % GATES;
        g_Wt[idx] = W[g * EMB + e];
    }
}

// ---------------- x-projection GEMM ----------------
__global__ void k_xproj(const int* __restrict__ seq,
                        const float* __restrict__ emb,
                        const float* __restrict__ bih0,
                        const float* __restrict__ bhh0) {
    __shared__ __align__(16) float embs[16][304];
    int g  = blockIdx.x * 128 + threadIdx.x;
    int t0 = blockIdx.y * 16;

    for (int idx = threadIdx.x; idx < 16 * 304; idx += 128) {
        int tt = idx / 304, e = idx % 304;
        float v = 0.f;
        if (e < EMB) v = emb[(size_t)seq[t0 + tt] * EMB + e];
        embs[tt][e] = v;
    }
    __syncthreads();

    float acc[16];
    float b = (g < GATES) ? (bih0[g] + bhh0[g]) : 0.f;
#pragma unroll
    for (int tt = 0; tt < 16; tt++) acc[tt] = b;

    for (int e4 = 0; e4 < 75; e4++) {
        float w0 = 0.f, w1 = 0.f, w2 = 0.f, w3 = 0.f;
        if (g < GATES) {
            w0 = g_Wt[(e4 * 4 + 0) * GATES + g];
            w1 = g_Wt[(e4 * 4 + 1) * GATES + g];
            w2 = g_Wt[(e4 * 4 + 2) * GATES + g];
            w3 = g_Wt[(e4 * 4 + 3) * GATES + g];
        }
#pragma unroll
        for (int tt = 0; tt < 16; tt++) {
            float4 ev = *reinterpret_cast<const float4*>(&embs[tt][e4 * 4]);
            acc[tt] = fmaf(ev.x, w0, fmaf(ev.y, w1, fmaf(ev.z, w2, fmaf(ev.w, w3, acc[tt]))));
        }
    }
    if (g < GATES) {
#pragma unroll
        for (int tt = 0; tt < 16; tt++)
            g_xp0[(size_t)(t0 + tt) * GATES + g] = acc[tt];
    }
}

__device__ __forceinline__ float sigf(float x)     { return 1.f / (1.f + __expf(-x)); }
__device__ __forceinline__ float tanhfast(float x) { return 1.f - 2.f / (__expf(2.f * x) + 1.f); }

// ---------------- persistent 2-layer LSTM recurrence (R6 + probe) ----------------
__global__ __launch_bounds__(THREADS, 1)
void k_lstm(const float* __restrict__ Whh0,
            const float* __restrict__ Wih1,
            const float* __restrict__ Whh1,
            const float* __restrict__ bih1,
            const float* __restrict__ bhh1) {
    int b   = blockIdx.x;
    int tid = threadIdx.x;
    int w = tid >> 5, l = tid & 31;

    __shared__ float sums[2][48];
    float wreg[6][16];

    if (b < NB0) {
        // ======================= LAYER 0 =======================
        const int ub = b * U0;
        const int grp = b & 7;
#pragma unroll
        for (int j = 0; j < RPW0; j++) {
            int r = w * RPW0 + j;
            int q = r / U0, u = r % U0;
            int grow = q * HID + ub + u;
#pragma unroll
            for (int k = 0; k < 16; k++) {
                int idx = l + 32 * k;
                wreg[j][k] = (idx < HID) ? Whh0[grow * HID + idx] : 0.f;
            }
        }
        float c = 0.f;
        const int need1 = (l < NGRP) ? quota1(l) : 0;

        for (int t = 0; t < TSEQ; t++) {
            float xp0v = 0.f, xp1v = 0.f, xp2v = 0.f, xp3v = 0.f;
            if (tid < U0) {
                const float* xp = &g_xp0[(size_t)t * GATES + ub + tid];
                xp0v = __ldcg(xp + 0 * HID);
                xp1v = __ldcg(xp + 1 * HID);
                xp2v = __ldcg(xp + 2 * HID);
                xp3v = __ldcg(xp + 3 * HID);
            }

            {
                const int* cp = &g_c1[t * NGRP + (l & 7)];
                for (;;) {
                    int v = (l < NGRP) ? ld_acq(cp) : 0;
                    if (__all_sync(0xffffffffu, v >= need1)) break;
                }
                __syncwarp();
            }

            const float* hr = &g_h1[(size_t)t * HP];
            float x[16];
#pragma unroll
            for (int k = 0; k < 16; k++) x[k] = __ldcg(hr + l + 32 * k);

            float* sb = sums[t & 1];
#pragma unroll
            for (int j = 0; j < RPW0; j++) {
                float acc = 0.f;
#pragma unroll
                for (int k = 0; k < 16; k++) acc = fmaf(wreg[j][k], x[k], acc);
#pragma unroll
                for (int off = 16; off; off >>= 1)
                    acc += __shfl_xor_sync(0xffffffffu, acc, off);
                if (l == 0) sb[w * RPW0 + j] = acc;
            }
            __syncthreads();

            if (w == 0) {
                if (l < U0) {
                    float pi = sb[0 * U0 + l] + xp0v;
                    float pf = sb[1 * U0 + l] + xp1v;
                    float pg = sb[2 * U0 + l] + xp2v;
                    float po = sb[3 * U0 + l] + xp3v;
                    float ig = sigf(pi), fg = sigf(pf), og = sigf(po);
                    float gg = tanhfast(pg);
                    c = fg * c + ig * gg;
                    // ---- PROBE: ~1100-cycle serial chain on the store path ----
                    float h = og * tanhfast(c) + probe_chain(pg);
                    __stcg(&g_h1[(size_t)(t + 1) * HP + ub + l], h);
                }
                __syncwarp();
                if (l == 0) red_release(&g_c1[(t + 1) * NGRP + grp]);
            }
        }
    } else {
        // ======================= LAYER 1 =======================
        const int bb = b - NB0;
        const int ub = bb * U1;
        const int grp = bb & 7;
#pragma unroll
        for (int j = 0; j < RPW1; j++) {
            int hr = w * RPW1 + j;
            int rl = hr % 24;
            int q = rl / U1, u = rl % U1;
            int ug = ub + u;
            int grow = q * HID + ug;
            const float* W = (hr >= 24) ? Whh1 : Wih1;
#pragma unroll
            for (int k = 0; k < 16; k++) {
                int idx = l + 32 * k;
                wreg[j][k] = (ug < HID && idx < HID) ? W[grow * HID + idx] : 0.f;
            }
        }
        float bg0 = 0.f, bg1 = 0.f, bg2 = 0.f, bg3 = 0.f, c = 0.f;
        if (tid < U1 && (ub + tid) < HID) {
            int base = ub + tid;
            bg0 = bih1[0 * HID + base] + bhh1[0 * HID + base];
            bg1 = bih1[1 * HID + base] + bhh1[1 * HID + base];
            bg2 = bih1[2 * HID + base] + bhh1[2 * HID + base];
            bg3 = bih1[3 * HID + base] + bhh1[3 * HID + base];
        }
        const int need = (l < NGRP) ? quota1(l)
                       : (l < 2 * NGRP) ? quota2(l - NGRP) : 0;

        for (int t = 0; t < TSEQ; t++) {
            {
                const int* cp1 = &g_c1[(t + 1) * NGRP + (l & 7)];
                const int* cp2 = &g_c2[t * NGRP + (l & 7)];
                for (;;) {
                    int v = (l < NGRP) ? ld_acq(cp1)
                          : (l < 2 * NGRP) ? ld_acq(cp2) : 0;
                    if (__all_sync(0xffffffffu, v >= need)) break;
                }
                __syncwarp();
            }

            const float* xs = (w < 4) ? &g_h1[(size_t)(t + 1) * HP]
                                      : &g_h2[(size_t)t * HP];
            float x[16];
#pragma unroll
            for (int k = 0; k < 16; k++) x[k] = __ldcg(xs + l + 32 * k);

            float* sb = sums[t & 1];
#pragma unroll
            for (int j = 0; j < RPW1; j++) {
                float acc = 0.f;
#pragma unroll
                for (int k = 0; k < 16; k++) acc = fmaf(wreg[j][k], x[k], acc);
#pragma unroll
                for (int off = 16; off; off >>= 1)
                    acc += __shfl_xor_sync(0xffffffffu, acc, off);
                if (l == 0) sb[w * RPW1 + j] = acc;
            }
            __syncthreads();

            if (w == 0) {
                if (l < U1) {
                    float pi = sb[0 * U1 + l] + sb[24 + 0 * U1 + l] + bg0;
                    float pf = sb[1 * U1 + l] + sb[24 + 1 * U1 + l] + bg1;
                    float pg = sb[2 * U1 + l] + sb[24 + 2 * U1 + l] + bg2;
                    float po = sb[3 * U1 + l] + sb[24 + 3 * U1 + l] + bg3;
                    float ig = sigf(pi), fg = sigf(pf), og = sigf(po);
                    float gg = tanhfast(pg);
                    c = fg * c + ig * gg;
                    // ---- PROBE: ~1100-cycle serial chain on the store path ----
                    float h = og * tanhfast(c) + probe_chain(pg);
                    if ((ub + l) < HID)
                        __stcg(&g_h2[(size_t)(t + 1) * HP + ub + l], h);
                }
                __syncwarp();
                if (l == 0) red_release(&g_c2[(t + 1) * NGRP + grp]);
            }
        }
    }
}

// ---------------- final FC ----------------
__global__ void k_fc(const float* __restrict__ fcW,
                     const float* __restrict__ fcb,
                     float* __restrict__ out) {
    int b = blockIdx.x;
    int l = threadIdx.x;
    float acc = 0.f;
    for (int k = l; k < HID; k += 32)
        acc += fcW[b * HID + k] * g_h2[TSEQ * HP + k];
#pragma unroll
    for (int off = 16; off; off >>= 1)
        acc += __shfl_xor_sync(0xffffffffu, acc, off);
    if (l == 0) out[b] = acc + fcb[b];
}

// ---------------- launch ----------------
extern "C" void kernel_launch(void* const* d_in, const int* in_sizes, int n_in,
                              void* d_out, int out_size) {
    const int*   seq  = (const int*)  d_in[0];
    const float* emb  = (const float*)d_in[1];
    const float* Wih0 = (const float*)d_in[2];
    const float* Whh0 = (const float*)d_in[3];
    const float* bih0 = (const float*)d_in[4];
    const float* bhh0 = (const float*)d_in[5];
    const float* Wih1 = (const float*)d_in[6];
    const float* Whh1 = (const float*)d_in[7];
    const float* bih1 = (const float*)d_in[8];
    const float* bhh1 = (const float*)d_in[9];
    const float* fcW  = (const float*)d_in[10];
    const float* fcb  = (const float*)d_in[11];

    k_init<<<64, 256>>>();
    k_transpose<<<(EMB * GATES + 255) / 256, 256>>>(Wih0);
    dim3 gx(16, 256);
    k_xproj<<<gx, 128>>>(seq, emb, bih0, bhh0);
    k_lstm<<<NBLK, THREADS>>>(Whh0, Wih1, Whh1, bih1, bhh1);
    k_fc<<<NCLS, 32>>>(fcW, fcb, (float*)d_out);
}

// round 15
// speedup vs baseline: 1.1844x; 1.1844x over previous
#include <cuda_runtime.h>
#include <cstdint>

// ---------------- problem constants ----------------
#define TSEQ   4096
#define EMB    300
#define HID    500
#define HP     512            // padded hidden (pad 500..511 never written -> stays 0)
#define GATES  2000           // 4*HID, torch gate order i,f,g,o
#define NCLS   90

// ---------------- persistent-kernel config (R6 champion topology) ----------------
#define NB0    50             // layer-0 CTAs, 10 units each
#define U0     10
#define RPW0   5              // 40 rows / 8 warps
#define NB1    84             // layer-1 CTAs, 6 units each
#define U1     6
#define RPW1   6              // 48 half-rows / 8 warps
#define NBLK   (NB0 + NB1)    // 134 <= 148
#define THREADS 256

#define NGRP   16             // counter groups per layer (64B = 2-sector row)
// quotas: 50 = 2*4 + 14*3 ; 84 = 4*6 + 12*5  (group = producer_index & 15)
__device__ __forceinline__ int quota1(int g) { return (g < 2) ? 4 : 3; }
__device__ __forceinline__ int quota2(int g) { return (g < 4) ? 6 : 5; }

// ---------------- device scratch ----------------
__device__ float g_xp0[(size_t)TSEQ * GATES];
__device__ float g_h1[(TSEQ + 1) * HP];             // row 0 = zeros (never rewritten)
__device__ float g_h2[(TSEQ + 1) * HP];
__device__ int   g_c1[(TSEQ + 1) * NGRP];
__device__ int   g_c2[(TSEQ + 1) * NGRP];
__device__ float g_Wt[EMB * GATES];

// ---------------- primitives ----------------
__device__ __forceinline__ int ld_acq(const int* p) {
    int v;
    asm volatile("ld.acquire.gpu.global.b32 %0, [%1];" : "=r"(v) : "l"(p) : "memory");
    return v;
}
__device__ __forceinline__ void red_release(int* p) {
    asm volatile("red.release.gpu.global.add.u32 [%0], 1;" :: "l"(p) : "memory");
}

// ---------------- init: reset counters every replay ----------------
__global__ void k_init() {
    const int n = (TSEQ + 1) * NGRP;
    for (int i = blockIdx.x * blockDim.x + threadIdx.x; i < 2 * n;
         i += gridDim.x * blockDim.x) {
        if (i < n) g_c1[i] = (i < NGRP) ? quota1(i & 15) : 0;      // row 0 = ready
        else { int j = i - n; g_c2[j] = (j < NGRP) ? quota2(j & 15) : 0; }
    }
}

// ---------------- transpose W_ih0 [2000,300] -> [300,2000] ----------------
__global__ void k_transpose(const float* __restrict__ W) {
    int idx = blockIdx.x * 256 + threadIdx.x;
    if (idx < EMB * GATES) {
        int e = idx / GATES;
        int g = idx % GATES;
        g_Wt[idx] = W[g * EMB + e];
    }
}

// ---------------- x-projection GEMM (unchanged) ----------------
__global__ void k_xproj(const int* __restrict__ seq,
                        const float* __restrict__ emb,
                        const float* __restrict__ bih0,
                        const float* __restrict__ bhh0) {
    __shared__ __align__(16) float embs[16][304];
    int g  = blockIdx.x * 128 + threadIdx.x;
    int t0 = blockIdx.y * 16;

    for (int idx = threadIdx.x; idx < 16 * 304; idx += 128) {
        int tt = idx / 304, e = idx % 304;
        float v = 0.f;
        if (e < EMB) v = emb[(size_t)seq[t0 + tt] * EMB + e];
        embs[tt][e] = v;
    }
    __syncthreads();

    float acc[16];
    float b = (g < GATES) ? (bih0[g] + bhh0[g]) : 0.f;
#pragma unroll
    for (int tt = 0; tt < 16; tt++) acc[tt] = b;

    for (int e4 = 0; e4 < 75; e4++) {
        float w0 = 0.f, w1 = 0.f, w2 = 0.f, w3 = 0.f;
        if (g < GATES) {
            w0 = g_Wt[(e4 * 4 + 0) * GATES + g];
            w1 = g_Wt[(e4 * 4 + 1) * GATES + g];
            w2 = g_Wt[(e4 * 4 + 2) * GATES + g];
            w3 = g_Wt[(e4 * 4 + 3) * GATES + g];
        }
#pragma unroll
        for (int tt = 0; tt < 16; tt++) {
            float4 ev = *reinterpret_cast<const float4*>(&embs[tt][e4 * 4]);
            acc[tt] = fmaf(ev.x, w0, fmaf(ev.y, w1, fmaf(ev.z, w2, fmaf(ev.w, w3, acc[tt]))));
        }
    }
    if (g < GATES) {
#pragma unroll
        for (int tt = 0; tt < 16; tt++)
            g_xp0[(size_t)(t0 + tt) * GATES + g] = acc[tt];
    }
}

__device__ __forceinline__ float sigf(float x)     { return 1.f / (1.f + __expf(-x)); }
__device__ __forceinline__ float tanhfast(float x) { return 1.f - 2.f / (__expf(2.f * x) + 1.f); }

// vectorized x-row load: lane l gets cols 128*q + 4*l + r as x[4*q + r]  (4x LDG.128)
__device__ __forceinline__ void load16v(const float* __restrict__ hr, int l, float (&x)[16]) {
#pragma unroll
    for (int q = 0; q < 4; q++) {
        float4 v = __ldcg(reinterpret_cast<const float4*>(hr + 128 * q + 4 * l));
        x[4 * q + 0] = v.x; x[4 * q + 1] = v.y;
        x[4 * q + 2] = v.z; x[4 * q + 3] = v.w;
    }
}
// weight column matching load16v mapping
__device__ __forceinline__ int colmap(int k, int l) { return 128 * (k >> 2) + 4 * l + (k & 3); }

// warp butterfly sum (proven R6 path)
__device__ __forceinline__ float warpsum(float acc) {
#pragma unroll
    for (int off = 16; off; off >>= 1)
        acc += __shfl_xor_sync(0xffffffffu, acc, off);
    return acc;
}

// ---------------- persistent 2-layer LSTM recurrence ----------------
__global__ __launch_bounds__(THREADS, 1)
void k_lstm(const float* __restrict__ Whh0,
            const float* __restrict__ Wih1,
            const float* __restrict__ Whh1,
            const float* __restrict__ bih1,
            const float* __restrict__ bhh1) {
    int b   = blockIdx.x;
    int tid = threadIdx.x;
    int w = tid >> 5, l = tid & 31;

    __shared__ float sums[2][48];
    float wreg[6][16];

    if (b < NB0) {
        // ======================= LAYER 0 =======================
        const int ub = b * U0;
        const int grp = b & 15;
#pragma unroll
        for (int j = 0; j < RPW0; j++) {
            int r = w * RPW0 + j;
            int q = r / U0, u = r % U0;
            int grow = q * HID + ub + u;
#pragma unroll
            for (int k = 0; k < 16; k++) {
                int col = colmap(k, l);
                wreg[j][k] = (col < HID) ? Whh0[(size_t)grow * HID + col] : 0.f;
            }
        }
        float c = 0.f;
        const int need1 = (l < NGRP) ? quota1(l) : 0;

        for (int t = 0; t < TSEQ; t++) {
            // xp prefetch (independent data; latency hides under wait)
            float xp0v = 0.f, xp1v = 0.f, xp2v = 0.f, xp3v = 0.f;
            if (tid < U0) {
                const float* xp = &g_xp0[(size_t)t * GATES + ub + tid];
                xp0v = __ldcg(xp + 0 * HID);
                xp1v = __ldcg(xp + 1 * HID);
                xp2v = __ldcg(xp + 2 * HID);
                xp3v = __ldcg(xp + 3 * HID);
            }

            // lanes 0-15 watch the 16 group counters (2 sectors)
            {
                const int* cp = &g_c1[t * NGRP + (l & 15)];
                for (;;) {
                    int v = (l < NGRP) ? ld_acq(cp) : 0;
                    if (__all_sync(0xffffffffu, v >= need1)) break;
                }
                __syncwarp();
            }

            float x[16];
            load16v(&g_h1[(size_t)t * HP], l, x);

            float* sb = sums[t & 1];
#pragma unroll
            for (int j = 0; j < RPW0; j++) {
                float acc = 0.f;
#pragma unroll
                for (int k = 0; k < 16; k++) acc = fmaf(wreg[j][k], x[k], acc);
                acc = warpsum(acc);
                if (l == 0) sb[w * RPW0 + j] = acc;
            }
            __syncthreads();

            if (w == 0) {
                if (l < U0) {
                    float pi = sb[0 * U0 + l] + xp0v;
                    float pf = sb[1 * U0 + l] + xp1v;
                    float pg = sb[2 * U0 + l] + xp2v;
                    float po = sb[3 * U0 + l] + xp3v;
                    float ig = sigf(pi), fg = sigf(pf), og = sigf(po);
                    float gg = tanhfast(pg);
                    c = fg * c + ig * gg;
                    __stcg(&g_h1[(size_t)(t + 1) * HP + ub + l], og * tanhfast(c));
                }
                __syncwarp();
                if (l == 0) red_release(&g_c1[(t + 1) * NGRP + grp]);
            }
        }
    } else {
        // ======================= LAYER 1 =======================
        const int bb = b - NB0;
        const int ub = bb * U1;
        const int grp = bb & 15;
#pragma unroll
        for (int j = 0; j < RPW1; j++) {
            int hr = w * RPW1 + j;             // [0,24)=W_ih1 (x=h1), [24,48)=W_hh1 (x=h2)
            int rl = hr % 24;
            int q = rl / U1, u = rl % U1;
            int ug = ub + u;
            int grow = q * HID + (ug < HID ? ug : 0);
            const float* W = (hr >= 24) ? Whh1 : Wih1;
#pragma unroll
            for (int k = 0; k < 16; k++) {
                int col = colmap(k, l);
                wreg[j][k] = (ug < HID && col < HID) ? W[(size_t)grow * HID + col] : 0.f;
            }
        }
        float bg0 = 0.f, bg1 = 0.f, bg2 = 0.f, bg3 = 0.f, c = 0.f;
        if (tid < U1 && (ub + tid) < HID) {
            int base = ub + tid;
            bg0 = bih1[0 * HID + base] + bhh1[0 * HID + base];
            bg1 = bih1[1 * HID + base] + bhh1[1 * HID + base];
            bg2 = bih1[2 * HID + base] + bhh1[2 * HID + base];
            bg3 = bih1[3 * HID + base] + bhh1[3 * HID + base];
        }
        // lanes 0-15: c1 row t+1 (quota1); lanes 16-31: c2 row t (quota2)
        const int need = (l < NGRP) ? quota1(l) : quota2(l & 15);

        for (int t = 0; t < TSEQ; t++) {
            {
                const int* cp1 = &g_c1[(t + 1) * NGRP + (l & 15)];
                const int* cp2 = &g_c2[t * NGRP + (l & 15)];
                for (;;) {
                    int v = (l < NGRP) ? ld_acq(cp1) : ld_acq(cp2);
                    if (__all_sync(0xffffffffu, v >= need)) break;
                }
                __syncwarp();
            }

            const float* xs = (w < 4) ? &g_h1[(size_t)(t + 1) * HP]
                                      : &g_h2[(size_t)t * HP];
            float x[16];
            load16v(xs, l, x);

            float* sb = sums[t & 1];
#pragma unroll
            for (int j = 0; j < RPW1; j++) {
                float acc = 0.f;
#pragma unroll
                for (int k = 0; k < 16; k++) acc = fmaf(wreg[j][k], x[k], acc);
                acc = warpsum(acc);
                if (l == 0) sb[w * RPW1 + j] = acc;
            }
            __syncthreads();

            if (w == 0) {
                if (l < U1) {
                    float pi = sb[0 * U1 + l] + sb[24 + 0 * U1 + l] + bg0;
                    float pf = sb[1 * U1 + l] + sb[24 + 1 * U1 + l] + bg1;
                    float pg = sb[2 * U1 + l] + sb[24 + 2 * U1 + l] + bg2;
                    float po = sb[3 * U1 + l] + sb[24 + 3 * U1 + l] + bg3;
                    float ig = sigf(pi), fg = sigf(pf), og = sigf(po);
                    float gg = tanhfast(pg);
                    c = fg * c + ig * gg;
                    if ((ub + l) < HID)
                        __stcg(&g_h2[(size_t)(t + 1) * HP + ub + l], og * tanhfast(c));
                }
                __syncwarp();
                if (l == 0) red_release(&g_c2[(t + 1) * NGRP + grp]);
            }
        }
    }
}

// ---------------- final FC ----------------
__global__ void k_fc(const float* __restrict__ fcW,
                     const float* __restrict__ fcb,
                     float* __restrict__ out) {
    int b = blockIdx.x;
    int l = threadIdx.x;
    float acc = 0.f;
    for (int k = l; k < HID; k += 32)
        acc += fcW[b * HID + k] * g_h2[TSEQ * HP + k];
#pragma unroll
    for (int off = 16; off; off >>= 1)
        acc += __shfl_xor_sync(0xffffffffu, acc, off);
    if (l == 0) out[b] = acc + fcb[b];
}

// ---------------- launch ----------------
extern "C" void kernel_launch(void* const* d_in, const int* in_sizes, int n_in,
                              void* d_out, int out_size) {
    const int*   seq  = (const int*)  d_in[0];
    const float* emb  = (const float*)d_in[1];
    const float* Wih0 = (const float*)d_in[2];
    const float* Whh0 = (const float*)d_in[3];
    const float* bih0 = (const float*)d_in[4];
    const float* bhh0 = (const float*)d_in[5];
    const float* Wih1 = (const float*)d_in[6];
    const float* Whh1 = (const float*)d_in[7];
    const float* bih1 = (const float*)d_in[8];
    const float* bhh1 = (const float*)d_in[9];
    const float* fcW  = (const float*)d_in[10];
    const float* fcb  = (const float*)d_in[11];

    k_init<<<64, 256>>>();
    k_transpose<<<(EMB * GATES + 255) / 256, 256>>>(Wih0);
    dim3 gx(16, 256);
    k_xproj<<<gx, 128>>>(seq, emb, bih0, bhh0);
    k_lstm<<<NBLK, THREADS>>>(Whh0, Wih1, Whh1, bih1, bhh1);
    k_fc<<<NCLS, 32>>>(fcW, fcb, (float*)d_out);
}

// round 16
// speedup vs baseline: 1.2863x; 1.0860x over previous
#include <cuda_runtime.h>
#include <cstdint>

// ---------------- problem constants ----------------
#define TSEQ   4096
#define EMB    300
#define HID    500
#define HP     512            // padded hidden (pad 500..511 never written -> stays 0)
#define GATES  2000           // 4*HID, torch gate order i,f,g,o
#define NCLS   90

// ---------------- persistent-kernel config (R6 champion topology) ----------------
#define NB0    50             // layer-0 CTAs, 10 units each
#define U0     10
#define RPW0   5              // 40 rows / 8 warps
#define NB1    84             // layer-1 CTAs, 6 units each
#define U1     6
#define RPW1   6              // 48 half-rows / 8 warps
#define NBLK   (NB0 + NB1)    // 134 <= 148
#define THREADS 256

#define NGRP   16             // counter groups per layer (64B = 2-sector row)
// quotas: 50 = 2*4 + 14*3 ; 84 = 4*6 + 12*5  (group = producer_index & 15)
__device__ __forceinline__ int quota1(int g) { return (g < 2) ? 4 : 3; }
__device__ __forceinline__ int quota2(int g) { return (g < 4) ? 6 : 5; }

// ---------------- device scratch ----------------
__device__ float g_xp0[(size_t)TSEQ * GATES];
__device__ float g_h1[(TSEQ + 1) * HP];             // row 0 = zeros (never rewritten)
__device__ float g_h2[(TSEQ + 1) * HP];
__device__ int   g_c1[(TSEQ + 1) * NGRP];
__device__ int   g_c2[(TSEQ + 1) * NGRP];
__device__ float g_Wt[EMB * GATES];

// ---------------- primitives ----------------
__device__ __forceinline__ int ld_acq(const int* p) {
    int v;
    asm volatile("ld.acquire.gpu.global.b32 %0, [%1];" : "=r"(v) : "l"(p) : "memory");
    return v;
}
__device__ __forceinline__ void red_release(int* p) {
    asm volatile("red.release.gpu.global.add.u32 [%0], 1;" :: "l"(p) : "memory");
}

// ---------------- init: reset counters every replay ----------------
__global__ void k_init() {
    const int n = (TSEQ + 1) * NGRP;
    for (int i = blockIdx.x * blockDim.x + threadIdx.x; i < 2 * n;
         i += gridDim.x * blockDim.x) {
        if (i < n) g_c1[i] = (i < NGRP) ? quota1(i & 15) : 0;      // row 0 = ready
        else { int j = i - n; g_c2[j] = (j < NGRP) ? quota2(j & 15) : 0; }
    }
}

// ---------------- transpose W_ih0 [2000,300] -> [300,2000] ----------------
__global__ void k_transpose(const float* __restrict__ W) {
    int idx = blockIdx.x * 256 + threadIdx.x;
    if (idx < EMB * GATES) {
        int e = idx / GATES;
        int g = idx % GATES;
        g_Wt[idx] = W[g * EMB + e];
    }
}

// ---------------- x-projection GEMM (unchanged) ----------------
__global__ void k_xproj(const int* __restrict__ seq,
                        const float* __restrict__ emb,
                        const float* __restrict__ bih0,
                        const float* __restrict__ bhh0) {
    __shared__ __align__(16) float embs[16][304];
    int g  = blockIdx.x * 128 + threadIdx.x;
    int t0 = blockIdx.y * 16;

    for (int idx = threadIdx.x; idx < 16 * 304; idx += 128) {
        int tt = idx / 304, e = idx % 304;
        float v = 0.f;
        if (e < EMB) v = emb[(size_t)seq[t0 + tt] * EMB + e];
        embs[tt][e] = v;
    }
    __syncthreads();

    float acc[16];
    float b = (g < GATES) ? (bih0[g] + bhh0[g]) : 0.f;
#pragma unroll
    for (int tt = 0; tt < 16; tt++) acc[tt] = b;

    for (int e4 = 0; e4 < 75; e4++) {
        float w0 = 0.f, w1 = 0.f, w2 = 0.f, w3 = 0.f;
        if (g < GATES) {
            w0 = g_Wt[(e4 * 4 + 0) * GATES + g];
            w1 = g_Wt[(e4 * 4 + 1) * GATES + g];
            w2 = g_Wt[(e4 * 4 + 2) * GATES + g];
            w3 = g_Wt[(e4 * 4 + 3) * GATES + g];
        }
#pragma unroll
        for (int tt = 0; tt < 16; tt++) {
            float4 ev = *reinterpret_cast<const float4*>(&embs[tt][e4 * 4]);
            acc[tt] = fmaf(ev.x, w0, fmaf(ev.y, w1, fmaf(ev.z, w2, fmaf(ev.w, w3, acc[tt]))));
        }
    }
    if (g < GATES) {
#pragma unroll
        for (int tt = 0; tt < 16; tt++)
            g_xp0[(size_t)(t0 + tt) * GATES + g] = acc[tt];
    }
}

__device__ __forceinline__ float sigf(float x)     { return 1.f / (1.f + __expf(-x)); }
__device__ __forceinline__ float tanhfast(float x) { return 1.f - 2.f / (__expf(2.f * x) + 1.f); }

// vectorized x-row load: lane l gets cols 128*q + 4*l + r as x[4*q + r]  (4x LDG.128)
__device__ __forceinline__ void load16v(const float* __restrict__ hr, int l, float (&x)[16]) {
#pragma unroll
    for (int q = 0; q < 4; q++) {
        float4 v = __ldcg(reinterpret_cast<const float4*>(hr + 128 * q + 4 * l));
        x[4 * q + 0] = v.x; x[4 * q + 1] = v.y;
        x[4 * q + 2] = v.z; x[4 * q + 3] = v.w;
    }
}
// weight column matching load16v mapping
__device__ __forceinline__ int colmap(int k, int l) { return 128 * (k >> 2) + 4 * l + (k & 3); }

// warp butterfly sum (proven R6 path)
__device__ __forceinline__ float warpsum(float acc) {
#pragma unroll
    for (int off = 16; off; off >>= 1)
        acc += __shfl_xor_sync(0xffffffffu, acc, off);
    return acc;
}

// ---------------- persistent 2-layer LSTM recurrence ----------------
__global__ __launch_bounds__(THREADS, 1)
void k_lstm(const float* __restrict__ Whh0,
            const float* __restrict__ Wih1,
            const float* __restrict__ Whh1,
            const float* __restrict__ bih1,
            const float* __restrict__ bhh1) {
    int b   = blockIdx.x;
    int tid = threadIdx.x;
    int w = tid >> 5, l = tid & 31;

    __shared__ float sums[2][48];
    float wreg[6][16];

    if (b < NB0) {
        // ======================= LAYER 0 =======================
        const int ub = b * U0;
        const int grp = b & 15;
#pragma unroll
        for (int j = 0; j < RPW0; j++) {
            int r = w * RPW0 + j;
            int q = r / U0, u = r % U0;
            int grow = q * HID + ub + u;
#pragma unroll
            for (int k = 0; k < 16; k++) {
                int col = colmap(k, l);
                wreg[j][k] = (col < HID) ? Whh0[(size_t)grow * HID + col] : 0.f;
            }
        }
        float c = 0.f;
        const int need1 = (l < NGRP) ? quota1(l) : 0;

        for (int t = 0; t < TSEQ; t++) {
            // xp prefetch (independent data; latency hides under wait)
            float xp0v = 0.f, xp1v = 0.f, xp2v = 0.f, xp3v = 0.f;
            if (tid < U0) {
                const float* xp = &g_xp0[(size_t)t * GATES + ub + tid];
                xp0v = __ldcg(xp + 0 * HID);
                xp1v = __ldcg(xp + 1 * HID);
                xp2v = __ldcg(xp + 2 * HID);
                xp3v = __ldcg(xp + 3 * HID);
            }

            // lanes 0-15 watch the 16 group counters (2 sectors)
            {
                const int* cp = &g_c1[t * NGRP + (l & 15)];
                for (;;) {
                    int v = (l < NGRP) ? ld_acq(cp) : 0;
                    if (__all_sync(0xffffffffu, v >= need1)) break;
                }
                __syncwarp();
            }

            float x[16];
            load16v(&g_h1[(size_t)t * HP], l, x);

            float* sb = sums[t & 1];
#pragma unroll
            for (int j = 0; j < RPW0; j++) {
                float acc = 0.f;
#pragma unroll
                for (int k = 0; k < 16; k++) acc = fmaf(wreg[j][k], x[k], acc);
                acc = warpsum(acc);
                if (l == 0) sb[w * RPW0 + j] = acc;
            }
            __syncthreads();

            if (w == 0) {
                if (l < U0) {
                    float pi = sb[0 * U0 + l] + xp0v;
                    float pf = sb[1 * U0 + l] + xp1v;
                    float pg = sb[2 * U0 + l] + xp2v;
                    float po = sb[3 * U0 + l] + xp3v;
                    float ig = sigf(pi), fg = sigf(pf), og = sigf(po);
                    float gg = tanhfast(pg);
                    c = fg * c + ig * gg;
                    __stcg(&g_h1[(size_t)(t + 1) * HP + ub + l], og * tanhfast(c));
                }
                __syncwarp();
                if (l == 0) red_release(&g_c1[(t + 1) * NGRP + grp]);
            }
        }
    } else {
        // ======================= LAYER 1 =======================
        const int bb = b - NB0;
        const int ub = bb * U1;
        const int grp = bb & 15;
#pragma unroll
        for (int j = 0; j < RPW1; j++) {
            int hr = w * RPW1 + j;             // [0,24)=W_ih1 (x=h1), [24,48)=W_hh1 (x=h2)
            int rl = hr % 24;
            int q = rl / U1, u = rl % U1;
            int ug = ub + u;
            int grow = q * HID + (ug < HID ? ug : 0);
            const float* W = (hr >= 24) ? Whh1 : Wih1;
#pragma unroll
            for (int k = 0; k < 16; k++) {
                int col = colmap(k, l);
                wreg[j][k] = (ug < HID && col < HID) ? W[(size_t)grow * HID + col] : 0.f;
            }
        }
        float bg0 = 0.f, bg1 = 0.f, bg2 = 0.f, bg3 = 0.f, c = 0.f;
        if (tid < U1 && (ub + tid) < HID) {
            int base = ub + tid;
            bg0 = bih1[0 * HID + base] + bhh1[0 * HID + base];
            bg1 = bih1[1 * HID + base] + bhh1[1 * HID + base];
            bg2 = bih1[2 * HID + base] + bhh1[2 * HID + base];
            bg3 = bih1[3 * HID + base] + bhh1[3 * HID + base];
        }
        // lanes 0-15: c1 row t+1 (quota1); lanes 16-31: c2 row t (quota2)
        const int need = (l < NGRP) ? quota1(l) : quota2(l & 15);

        for (int t = 0; t < TSEQ; t++) {
            {
                const int* cp1 = &g_c1[(t + 1) * NGRP + (l & 15)];
                const int* cp2 = &g_c2[t * NGRP + (l & 15)];
                for (;;) {
                    int v = (l < NGRP) ? ld_acq(cp1) : ld_acq(cp2);
                    if (__all_sync(0xffffffffu, v >= need)) break;
                }
                __syncwarp();
            }

            const float* xs = (w < 4) ? &g_h1[(size_t)(t + 1) * HP]
                                      : &g_h2[(size_t)t * HP];
            float x[16];
            load16v(xs, l, x);

            float* sb = sums[t & 1];
#pragma unroll
            for (int j = 0; j < RPW1; j++) {
                float acc = 0.f;
#pragma unroll
                for (int k = 0; k < 16; k++) acc = fmaf(wreg[j][k], x[k], acc);
                acc = warpsum(acc);
                if (l == 0) sb[w * RPW1 + j] = acc;
            }
            __syncthreads();

            if (w == 0) {
                if (l < U1) {
                    float pi = sb[0 * U1 + l] + sb[24 + 0 * U1 + l] + bg0;
                    float pf = sb[1 * U1 + l] + sb[24 + 1 * U1 + l] + bg1;
                    float pg = sb[2 * U1 + l] + sb[24 + 2 * U1 + l] + bg2;
                    float po = sb[3 * U1 + l] + sb[24 + 3 * U1 + l] + bg3;
                    float ig = sigf(pi), fg = sigf(pf), og = sigf(po);
                    float gg = tanhfast(pg);
                    c = fg * c + ig * gg;
                    if ((ub + l) < HID)
                        __stcg(&g_h2[(size_t)(t + 1) * HP + ub + l], og * tanhfast(c));
                }
                __syncwarp();
                if (l == 0) red_release(&g_c2[(t + 1) * NGRP + grp]);
            }
        }
    }
}

// ---------------- final FC ----------------
__global__ void k_fc(const float* __restrict__ fcW,
                     const float* __restrict__ fcb,
                     float* __restrict__ out) {
    int b = blockIdx.x;
    int l = threadIdx.x;
    float acc = 0.f;
    for (int k = l; k < HID; k += 32)
        acc += fcW[b * HID + k] * g_h2[TSEQ * HP + k];
#pragma unroll
    for (int off = 16; off; off >>= 1)
        acc += __shfl_xor_sync(0xffffffffu, acc, off);
    if (l == 0) out[b] = acc + fcb[b];
}

// ---------------- launch ----------------
extern "C" void kernel_launch(void* const* d_in, const int* in_sizes, int n_in,
                              void* d_out, int out_size) {
    const int*   seq  = (const int*)  d_in[0];
    const float* emb  = (const float*)d_in[1];
    const float* Wih0 = (const float*)d_in[2];
    const float* Whh0 = (const float*)d_in[3];
    const float* bih0 = (const float*)d_in[4];
    const float* bhh0 = (const float*)d_in[5];
    const float* Wih1 = (const float*)d_in[6];
    const float* Whh1 = (const float*)d_in[7];
    const float* bih1 = (const float*)d_in[8];
    const float* bhh1 = (const float*)d_in[9];
    const float* fcW  = (const float*)d_in[10];
    const float* fcb  = (const float*)d_in[11];

    k_init<<<64, 256>>>();
    k_transpose<<<(EMB * GATES + 255) / 256, 256>>>(Wih0);
    dim3 gx(16, 256);
    k_xproj<<<gx, 128>>>(seq, emb, bih0, bhh0);
    k_lstm<<<NBLK, THREADS>>>(Whh0, Wih1, Whh1, bih1, bhh1);
    k_fc<<<NCLS, 32>>>(fcW, fcb, (float*)d_out);
}